// round 10
// baseline (speedup 1.0000x reference)
#include <cuda_runtime.h>
#include <cuda_bf16.h>
#include <cstdint>

// Problem dims
#define MTOT   16384      // BATCH*T = 8*2048
#define NN     512
#define TSEQ   2048
#define NBATCH 8
#define NCHUNK 64
#define CHUNKT 32

// ---------------- scratch (__device__ globals; no allocs allowed) -----------
__device__ float g_xre[(size_t)MTOT * NN];      // GEMM1 out / scan intermediate
__device__ float g_xim[(size_t)MTOT * NN];
__device__ float g_cre[NBATCH * NCHUNK * NN];
__device__ float g_cim[NBATCH * NCHUNK * NN];
__device__ float g_pre[NBATCH * NCHUNK * NN];
__device__ float g_pim[NBATCH * NCHUNK * NN];

// bf16-split operand panels (16B-aligned for cp.async)
__device__ __align__(16) __nv_bfloat16 g_uh[(size_t)MTOT * 512];
__device__ __align__(16) __nv_bfloat16 g_ul[(size_t)MTOT * 512];
__device__ __align__(16) __nv_bfloat16 g_xh[(size_t)MTOT * 1024];  // [x_re | x_im] hi
__device__ __align__(16) __nv_bfloat16 g_xl[(size_t)MTOT * 1024];  // [x_re | x_im] lo
// weights: g_B1 [1024 n'][512 k] = [(gamma B_re)^T ; (gamma B_im)^T]
//          g_B2 [512 n][1024 k]  = [C_re^T | (-C_im)^T]
__device__ __align__(16) __nv_bfloat16 g_B1hi[1024 * 512];
__device__ __align__(16) __nv_bfloat16 g_B1lo[1024 * 512];
__device__ __align__(16) __nv_bfloat16 g_B2hi[512 * 1024];
__device__ __align__(16) __nv_bfloat16 g_B2lo[512 * 1024];

// ---------------- helpers ---------------------------------------------------
__device__ __forceinline__ uint32_t smem_u32(const void* p) {
    uint32_t a;
    asm("{ .reg .u64 t; cvta.to.shared.u64 t, %1; cvt.u32.u64 %0, t; }"
        : "=r"(a) : "l"(p));
    return a;
}
__device__ __forceinline__ void ldsm4(uint32_t* r, uint32_t addr) {
    asm volatile("ldmatrix.sync.aligned.m8n8.x4.shared.b16 {%0,%1,%2,%3}, [%4];"
        : "=r"(r[0]), "=r"(r[1]), "=r"(r[2]), "=r"(r[3]) : "r"(addr));
}
__device__ __forceinline__ void mma_bf16(float* c, const uint32_t* a, const uint32_t* b) {
    asm volatile("mma.sync.aligned.m16n8k16.row.col.f32.bf16.bf16.f32 "
        "{%0,%1,%2,%3}, {%4,%5,%6,%7}, {%8,%9}, {%0,%1,%2,%3};"
        : "+f"(c[0]), "+f"(c[1]), "+f"(c[2]), "+f"(c[3])
        : "r"(a[0]), "r"(a[1]), "r"(a[2]), "r"(a[3]), "r"(b[0]), "r"(b[1]));
}
// L1-PRESERVING async copy (.ca — the .cg variant bypasses L1 and cost R8 ~80us)
__device__ __forceinline__ void cp16(uint32_t dst, const void* src) {
    asm volatile("cp.async.ca.shared.global [%0], [%1], 16;" :: "r"(dst), "l"(src));
}
__device__ __forceinline__ void cp_commit() {
    asm volatile("cp.async.commit_group;" ::: "memory");
}
template <int N> __device__ __forceinline__ void cp_wait() {
    asm volatile("cp.async.wait_group %0;" :: "n"(N) : "memory");
}
__device__ __forceinline__ void splitbf(float v, __nv_bfloat16& h, __nv_bfloat16& l) {
    h = __float2bfloat16(v);
    l = __float2bfloat16(v - __bfloat162float(h));
}
__device__ __forceinline__ void split2(float v, unsigned short& hb, unsigned short& lb) {
    __nv_bfloat16 h, l;
    splitbf(v, h, l);
    hb = *reinterpret_cast<unsigned short*>(&h);
    lb = *reinterpret_cast<unsigned short*>(&l);
}

// ============================================================================
// Prep: transpose + gamma-fold + bf16 split of the 4 weight matrices
// ============================================================================
__global__ void prep_kernel(const float* __restrict__ Bre, const float* __restrict__ Bim,
                            const float* __restrict__ Cre, const float* __restrict__ Cim,
                            const float* __restrict__ gamma)
{
    __shared__ float tile[32][33];
    const int z = blockIdx.z;
    const float* S = (z == 0) ? Bre : (z == 1) ? Bim : (z == 2) ? Cre : Cim;
    const int k0 = blockIdx.x * 32, n0 = blockIdx.y * 32;
    const int tx = threadIdx.x, ty = threadIdx.y;  // 32 x 8
#pragma unroll
    for (int i = 0; i < 32; i += 8)
        tile[ty + i][tx] = S[(size_t)(k0 + ty + i) * 512 + n0 + tx];
    __syncthreads();
#pragma unroll
    for (int i = 0; i < 32; i += 8) {
        int n = n0 + ty + i, k = k0 + tx;
        float v = tile[tx][ty + i];
        if (z < 2)  v *= gamma[k];
        if (z == 3) v = -v;
        __nv_bfloat16 h, l;
        splitbf(v, h, l);
        if (z == 0) { g_B1hi[(size_t)n * 512 + k] = h;          g_B1lo[(size_t)n * 512 + k] = l; }
        if (z == 1) { g_B1hi[(size_t)(512 + n) * 512 + k] = h;  g_B1lo[(size_t)(512 + n) * 512 + k] = l; }
        if (z == 2) { g_B2hi[(size_t)n * 1024 + k] = h;         g_B2lo[(size_t)n * 1024 + k] = l; }
        if (z == 3) { g_B2hi[(size_t)n * 1024 + 512 + k] = h;   g_B2lo[(size_t)n * 1024 + 512 + k] = l; }
    }
}

// ============================================================================
// Split u -> bf16 hi/lo panels (one-time)
// ============================================================================
__global__ __launch_bounds__(256) void split_u_kernel(const float* __restrict__ u)
{
    size_t i = ((size_t)blockIdx.x * 256 + threadIdx.x) * 8;
    float4 v0 = *(const float4*)(u + i);
    float4 v1 = *(const float4*)(u + i + 4);
    float f[8] = {v0.x, v0.y, v0.z, v0.w, v1.x, v1.y, v1.z, v1.w};
    uint32_t hw[4], lw[4];
#pragma unroll
    for (int j = 0; j < 4; j++) {
        unsigned short h0, l0, h1, l1;
        split2(f[2 * j], h0, l0);
        split2(f[2 * j + 1], h1, l1);
        hw[j] = (uint32_t)h0 | ((uint32_t)h1 << 16);
        lw[j] = (uint32_t)l0 | ((uint32_t)l1 << 16);
    }
    *(uint4*)&g_uh[i] = make_uint4(hw[0], hw[1], hw[2], hw[3]);
    *(uint4*)&g_ul[i] = make_uint4(lw[0], lw[1], lw[2], lw[3]);
}

// ============================================================================
// HMMA GEMM, split-bf16 fp32 emulation, cp.async.ca 4-stage pipeline.
// mode 0: D[16384,1024] = u @ B1^T           -> writes g_xre / g_xim (fp32)
// mode 1: D[16384, 512] = [x_re|x_im] @ B2^T -> out = D + Dvec*u
// CTA tile M=128 N=128 K=32; 8 warps (warp tile 32x64).
// Stage: A rows then B rows, each 128 rows x 128B (32 hi bf16 | 32 lo bf16),
// 16B granule g stored at (g ^ (row&7)).
// ============================================================================
#define NSTAGE      4
#define STAGE_BYTES 32768
#define SMEM_TOTAL  (NSTAGE * STAGE_BYTES)

__global__ __launch_bounds__(256, 1)
void gemm_tc(int mode, int kch, const float* __restrict__ u,
             const float* __restrict__ Dvec, float* __restrict__ out)
{
    extern __shared__ __align__(1024) char smem[];
    const int tid = threadIdx.x;
    const int lane = tid & 31, wid = tid >> 5;
    const int wm = wid >> 1, wn = wid & 1;      // 4 m-warps x 2 n-warps
    const int nBase = blockIdx.x * 128, mBase = blockIdx.y * 128;
    const uint32_t sb = smem_u32(smem);

    const __nv_bfloat16 *Ah, *Al, *Bh, *Bl;
    int lda, ldb;
    if (mode == 0) { Ah = g_uh; Al = g_ul; lda = 512;  Bh = g_B1hi; Bl = g_B1lo; ldb = 512; }
    else           { Ah = g_xh; Al = g_xl; lda = 1024; Bh = g_B2hi; Bl = g_B2lo; ldb = 1024; }

    // loader mapping: 2 threads per row; half 0 -> hi 64B, half 1 -> lo 64B
    const int r = tid >> 1, half = tid & 1;
    const int swz = r & 7;

    // ldmatrix lane mapping
    const int g = lane >> 3, lr = lane & 7;
    int aRow[2], bRow[4];
#pragma unroll
    for (int mf = 0; mf < 2; mf++) aRow[mf] = wm * 32 + mf * 16 + (g & 1) * 8 + lr;
#pragma unroll
    for (int np = 0; np < 4; np++) bRow[np] = wn * 64 + np * 16 + (g >> 1) * 8 + lr;
    const int aCk = g >> 1;
    const int bCk = g & 1;

    float acc[2][8][4];
#pragma unroll
    for (int i = 0; i < 2; i++)
#pragma unroll
        for (int j = 0; j < 8; j++)
#pragma unroll
            for (int q = 0; q < 4; q++) acc[i][j][q] = 0.f;

    auto ISSUE = [&](int c) {
        const uint32_t st = sb + (c % NSTAGE) * STAGE_BYTES;
        const __nv_bfloat16* as = (half ? Al : Ah) + (size_t)(mBase + r) * lda + c * 32;
        const __nv_bfloat16* bs = (half ? Bl : Bh) + (size_t)(nBase + r) * ldb + c * 32;
        const uint32_t rowA = st + r * 128;
        const uint32_t rowB = st + 16384 + r * 128;
#pragma unroll
        for (int j = 0; j < 4; j++)
            cp16(rowA + (((half * 4 + j) ^ swz) << 4), as + j * 8);
#pragma unroll
        for (int j = 0; j < 4; j++)
            cp16(rowB + (((half * 4 + j) ^ swz) << 4), bs + j * 8);
        cp_commit();
    };

    auto COMPUTE = [&](int s) {
        const uint32_t baseA = sb + s * STAGE_BYTES;
        const uint32_t baseB = baseA + 16384;
#pragma unroll
        for (int ks = 0; ks < 2; ks++) {
            uint32_t ah[2][4], al[2][4];
#pragma unroll
            for (int mf = 0; mf < 2; mf++) {
                const int rw = aRow[mf];
                ldsm4(ah[mf], baseA + rw * 128 + (((ks * 2 + aCk) ^ (rw & 7)) << 4));
                ldsm4(al[mf], baseA + rw * 128 + (((4 + ks * 2 + aCk) ^ (rw & 7)) << 4));
            }
            uint32_t bh[4][4], bl[4][4];
#pragma unroll
            for (int np = 0; np < 4; np++) {
                const int rw = bRow[np];
                ldsm4(bh[np], baseB + rw * 128 + (((ks * 2 + bCk) ^ (rw & 7)) << 4));
                ldsm4(bl[np], baseB + rw * 128 + (((4 + ks * 2 + bCk) ^ (rw & 7)) << 4));
            }
#pragma unroll
            for (int mf = 0; mf < 2; mf++)
#pragma unroll
                for (int np = 0; np < 4; np++) {
                    mma_bf16(acc[mf][2 * np],     ah[mf], &bh[np][0]);
                    mma_bf16(acc[mf][2 * np + 1], ah[mf], &bh[np][2]);
                    mma_bf16(acc[mf][2 * np],     ah[mf], &bl[np][0]);
                    mma_bf16(acc[mf][2 * np + 1], ah[mf], &bl[np][2]);
                    mma_bf16(acc[mf][2 * np],     al[mf], &bh[np][0]);
                    mma_bf16(acc[mf][2 * np + 1], al[mf], &bh[np][2]);
                }
        }
    };

#pragma unroll
    for (int c0 = 0; c0 < NSTAGE - 1; c0++)
        if (c0 < kch) ISSUE(c0);
    for (int c = 0; c < kch; c++) {
        cp_wait<NSTAGE - 2>();
        __syncthreads();
        if (c + NSTAGE - 1 < kch) ISSUE(c + NSTAGE - 1);
        COMPUTE(c % NSTAGE);
    }

    // ---- epilogue ----
    const int em = lane >> 2, en = (lane & 3) * 2;
#pragma unroll
    for (int mf = 0; mf < 2; mf++)
#pragma unroll
        for (int nf = 0; nf < 8; nf++) {
            const int m = mBase + wm * 32 + mf * 16 + em;
            const int n = nBase + wn * 64 + nf * 8 + en;
            const float* a4 = acc[mf][nf];
            if (mode == 0) {
                float* dst = (n < 512) ? g_xre : g_xim;
                const int nc = n & 511;
                *(float2*)&dst[(size_t)m * 512 + nc]       = make_float2(a4[0], a4[1]);
                *(float2*)&dst[(size_t)(m + 8) * 512 + nc] = make_float2(a4[2], a4[3]);
            } else {
                float2 dd = *(const float2*)&Dvec[n];
                float2 u0 = *(const float2*)&u[(size_t)m * 512 + n];
                float2 u1 = *(const float2*)&u[(size_t)(m + 8) * 512 + n];
                *(float2*)&out[(size_t)m * 512 + n] =
                    make_float2(a4[0] + dd.x * u0.x, a4[1] + dd.y * u0.y);
                *(float2*)&out[(size_t)(m + 8) * 512 + n] =
                    make_float2(a4[2] + dd.x * u1.x, a4[3] + dd.y * u1.y);
            }
        }
}

// ============================================================================
// Scan phase 1: per-chunk local scan, in place; chunk 0 emits final bf16 split.
// ============================================================================
__global__ __launch_bounds__(512) void scan_local_kernel(
    const float* __restrict__ nu, const float* __restrict__ theta)
{
    const int n = threadIdx.x;
    const int c = blockIdx.x;
    const int b = blockIdx.y;
    const float r = expf(-expf(nu[n]));
    const float th = theta[n];
    const float lre = r * cosf(th), lim = r * sinf(th);
    float xr = 0.f, xi = 0.f;
    const size_t m0 = (size_t)b * TSEQ + (size_t)c * CHUNKT;
    const size_t base = m0 * NN + n;
    if (c == 0) {
#pragma unroll
        for (int t = 0; t < CHUNKT; t++) {
            size_t idx = base + (size_t)t * NN;
            float ur = g_xre[idx], ui = g_xim[idx];
            float nr = lre * xr - lim * xi + ur;
            float ni = lre * xi + lim * xr + ui;
            xr = nr; xi = ni;
            size_t mo = (m0 + t) * 1024 + n;
            __nv_bfloat16 h, l;
            splitbf(xr, h, l); g_xh[mo] = h;       g_xl[mo] = l;
            splitbf(xi, h, l); g_xh[mo + 512] = h; g_xl[mo + 512] = l;
        }
    } else {
#pragma unroll
        for (int t = 0; t < CHUNKT; t++) {
            size_t idx = base + (size_t)t * NN;
            float ur = g_xre[idx], ui = g_xim[idx];
            float nr = lre * xr - lim * xi + ur;
            float ni = lre * xi + lim * xr + ui;
            xr = nr; xi = ni;
            g_xre[idx] = xr; g_xim[idx] = xi;
        }
    }
    int coff = (b * NCHUNK + c) * NN + n;
    g_cre[coff] = xr; g_cim[coff] = xi;
}

// ============================================================================
// Scan phase 2: inclusive prefix over chunk carries (fully unrolled)
// ============================================================================
__global__ __launch_bounds__(512) void scan_chunk_kernel(
    const float* __restrict__ nu, const float* __restrict__ theta)
{
    const int n = threadIdx.x;
    const int b = blockIdx.x;
    const float e = expf(nu[n]);
    const float rP = expf(-(float)CHUNKT * e);
    const float ang = (float)CHUNKT * theta[n];
    const float Lre = rP * cosf(ang), Lim = rP * sinf(ang);
    float pr = 0.f, pi = 0.f;
#pragma unroll
    for (int c = 0; c < NCHUNK; c++) {
        int off = (b * NCHUNK + c) * NN + n;
        float cr = g_cre[off], ci = g_cim[off];
        float nr = Lre * pr - Lim * pi + cr;
        float ni = Lre * pi + Lim * pr + ci;
        pr = nr; pi = ni;
        g_pre[off] = pr; g_pim[off] = pi;
    }
}

// ============================================================================
// Scan phase 3: fixup chunks >=1 and emit final bf16 split for GEMM2.
// ============================================================================
__global__ __launch_bounds__(512) void scan_fix_kernel(
    const float* __restrict__ nu, const float* __restrict__ theta)
{
    const int n = threadIdx.x;
    const int c = blockIdx.x + 1;
    const int b = blockIdx.y;
    const float r = expf(-expf(nu[n]));
    const float th = theta[n];
    const float lre = r * cosf(th), lim = r * sinf(th);
    int poff = (b * NCHUNK + (c - 1)) * NN + n;
    float mr = g_pre[poff], mi = g_pim[poff];
    const size_t m0 = (size_t)b * TSEQ + (size_t)c * CHUNKT;
    const size_t base = m0 * NN + n;
#pragma unroll
    for (int t = 0; t < CHUNKT; t++) {
        float tr = lre * mr - lim * mi;
        float ti = lre * mi + lim * mr;
        mr = tr; mi = ti;
        size_t idx = base + (size_t)t * NN;
        float xr = g_xre[idx] + mr;
        float xi = g_xim[idx] + mi;
        size_t mo = (m0 + t) * 1024 + n;
        __nv_bfloat16 h, l;
        splitbf(xr, h, l); g_xh[mo] = h;       g_xl[mo] = l;
        splitbf(xi, h, l); g_xh[mo + 512] = h; g_xl[mo + 512] = l;
    }
}

// ============================================================================
extern "C" void kernel_launch(void* const* d_in, const int* in_sizes, int n_in,
                              void* d_out, int out_size)
{
    const float* u     = (const float*)d_in[0];
    const float* C_re  = (const float*)d_in[1];
    const float* C_im  = (const float*)d_in[2];
    const float* B_re  = (const float*)d_in[3];
    const float* B_im  = (const float*)d_in[4];
    const float* D     = (const float*)d_in[5];
    const float* nu    = (const float*)d_in[6];
    const float* theta = (const float*)d_in[7];
    const float* gamma = (const float*)d_in[8];
    float* out = (float*)d_out;

    cudaFuncSetAttribute(gemm_tc, cudaFuncAttributeMaxDynamicSharedMemorySize, SMEM_TOTAL);

    prep_kernel<<<dim3(16, 16, 4), dim3(32, 8)>>>(B_re, B_im, C_re, C_im, gamma);
    split_u_kernel<<<(MTOT * 512) / (256 * 8), 256>>>(u);
    gemm_tc<<<dim3(8, 128), 256, SMEM_TOTAL>>>(0, 16, u, D, out);
    scan_local_kernel<<<dim3(NCHUNK, NBATCH), NN>>>(nu, theta);
    scan_chunk_kernel<<<NBATCH, NN>>>(nu, theta);
    scan_fix_kernel<<<dim3(NCHUNK - 1, NBATCH), NN>>>(nu, theta);
    gemm_tc<<<dim3(4, 128), 256, SMEM_TOTAL>>>(1, 32, u, D, out);
}

// round 11
// speedup vs baseline: 1.3822x; 1.3822x over previous
#include <cuda_runtime.h>
#include <cuda_bf16.h>
#include <cstdint>

// Problem dims
#define MTOT   16384      // BATCH*T = 8*2048
#define NN     512
#define TSEQ   2048
#define NBATCH 8
#define NCHUNK 64
#define CHUNKT 32

// ---------------- scratch (__device__ globals; no allocs allowed) -----------
__device__ float g_xre[(size_t)MTOT * NN];      // GEMM1 out / scan intermediate
__device__ float g_xim[(size_t)MTOT * NN];
__device__ float g_cre[NBATCH * NCHUNK * NN];
__device__ float g_cim[NBATCH * NCHUNK * NN];
__device__ float g_pre[NBATCH * NCHUNK * NN];
__device__ float g_pim[NBATCH * NCHUNK * NN];

// bf16-split operand panels
__device__ __align__(16) __nv_bfloat16 g_uh[(size_t)MTOT * 512];
__device__ __align__(16) __nv_bfloat16 g_ul[(size_t)MTOT * 512];
__device__ __align__(16) __nv_bfloat16 g_xh[(size_t)MTOT * 1024];  // [x_re | x_im] hi
__device__ __align__(16) __nv_bfloat16 g_xl[(size_t)MTOT * 1024];  // [x_re | x_im] lo
// weights: g_B1 [1024 n'][512 k] = [(gamma B_re)^T ; (gamma B_im)^T]
//          g_B2 [512 n][1024 k]  = [C_re^T | (-C_im)^T]
__device__ __align__(16) __nv_bfloat16 g_B1hi[1024 * 512];
__device__ __align__(16) __nv_bfloat16 g_B1lo[1024 * 512];
__device__ __align__(16) __nv_bfloat16 g_B2hi[512 * 1024];
__device__ __align__(16) __nv_bfloat16 g_B2lo[512 * 1024];

// ---------------- helpers ---------------------------------------------------
__device__ __forceinline__ uint32_t smem_u32(const void* p) {
    uint32_t a;
    asm("{ .reg .u64 t; cvta.to.shared.u64 t, %1; cvt.u32.u64 %0, t; }"
        : "=r"(a) : "l"(p));
    return a;
}
__device__ __forceinline__ void ldsm4(uint32_t* r, uint32_t addr) {
    asm volatile("ldmatrix.sync.aligned.m8n8.x4.shared.b16 {%0,%1,%2,%3}, [%4];"
        : "=r"(r[0]), "=r"(r[1]), "=r"(r[2]), "=r"(r[3]) : "r"(addr));
}
__device__ __forceinline__ void mma_bf16(float* c, const uint32_t* a, const uint32_t* b) {
    asm volatile("mma.sync.aligned.m16n8k16.row.col.f32.bf16.bf16.f32 "
        "{%0,%1,%2,%3}, {%4,%5,%6,%7}, {%8,%9}, {%0,%1,%2,%3};"
        : "+f"(c[0]), "+f"(c[1]), "+f"(c[2]), "+f"(c[3])
        : "r"(a[0]), "r"(a[1]), "r"(a[2]), "r"(a[3]), "r"(b[0]), "r"(b[1]));
}
__device__ __forceinline__ void splitbf(float v, __nv_bfloat16& h, __nv_bfloat16& l) {
    h = __float2bfloat16(v);
    l = __float2bfloat16(v - __bfloat162float(h));
}
__device__ __forceinline__ void split2(float v, unsigned short& hb, unsigned short& lb) {
    __nv_bfloat16 h, l;
    splitbf(v, h, l);
    hb = *reinterpret_cast<unsigned short*>(&h);
    lb = *reinterpret_cast<unsigned short*>(&l);
}

// ============================================================================
// Prep: transpose + gamma-fold + bf16 split of the 4 weight matrices
// ============================================================================
__global__ void prep_kernel(const float* __restrict__ Bre, const float* __restrict__ Bim,
                            const float* __restrict__ Cre, const float* __restrict__ Cim,
                            const float* __restrict__ gamma)
{
    __shared__ float tile[32][33];
    const int z = blockIdx.z;
    const float* S = (z == 0) ? Bre : (z == 1) ? Bim : (z == 2) ? Cre : Cim;
    const int k0 = blockIdx.x * 32, n0 = blockIdx.y * 32;
    const int tx = threadIdx.x, ty = threadIdx.y;  // 32 x 8
#pragma unroll
    for (int i = 0; i < 32; i += 8)
        tile[ty + i][tx] = S[(size_t)(k0 + ty + i) * 512 + n0 + tx];
    __syncthreads();
#pragma unroll
    for (int i = 0; i < 32; i += 8) {
        int n = n0 + ty + i, k = k0 + tx;
        float v = tile[tx][ty + i];
        if (z < 2)  v *= gamma[k];
        if (z == 3) v = -v;
        __nv_bfloat16 h, l;
        splitbf(v, h, l);
        if (z == 0) { g_B1hi[(size_t)n * 512 + k] = h;          g_B1lo[(size_t)n * 512 + k] = l; }
        if (z == 1) { g_B1hi[(size_t)(512 + n) * 512 + k] = h;  g_B1lo[(size_t)(512 + n) * 512 + k] = l; }
        if (z == 2) { g_B2hi[(size_t)n * 1024 + k] = h;         g_B2lo[(size_t)n * 1024 + k] = l; }
        if (z == 3) { g_B2hi[(size_t)n * 1024 + 512 + k] = h;   g_B2lo[(size_t)n * 1024 + 512 + k] = l; }
    }
}

// ============================================================================
// Split u -> bf16 hi/lo panels (one-time)
// ============================================================================
__global__ __launch_bounds__(256) void split_u_kernel(const float* __restrict__ u)
{
    size_t i = ((size_t)blockIdx.x * 256 + threadIdx.x) * 8;
    float4 v0 = *(const float4*)(u + i);
    float4 v1 = *(const float4*)(u + i + 4);
    float f[8] = {v0.x, v0.y, v0.z, v0.w, v1.x, v1.y, v1.z, v1.w};
    uint32_t hw[4], lw[4];
#pragma unroll
    for (int j = 0; j < 4; j++) {
        unsigned short h0, l0, h1, l1;
        split2(f[2 * j], h0, l0);
        split2(f[2 * j + 1], h1, l1);
        hw[j] = (uint32_t)h0 | ((uint32_t)h1 << 16);
        lw[j] = (uint32_t)l0 | ((uint32_t)l1 << 16);
    }
    *(uint4*)&g_uh[i] = make_uint4(hw[0], hw[1], hw[2], hw[3]);
    *(uint4*)&g_ul[i] = make_uint4(lw[0], lw[1], lw[2], lw[3]);
}

// ============================================================================
// HMMA GEMM, split-bf16 fp32 emulation. R7's proven LDG->register->STS
// double-buffer mainloop, but operands pre-split (loader = pure uint4 copies).
// mode 0: D[16384,1024] = u @ B1^T           -> writes g_xre / g_xim (fp32)
// mode 1: D[16384, 512] = [x_re|x_im] @ B2^T -> out = D + Dvec*u
// CTA tile M=128 N=128 K=32; 8 warps (warp tile 32x64); 2-stage smem.
// Stage: A rows then B rows, each 128 rows x 128B (32 hi bf16 | 32 lo bf16),
// 16B granule g stored at (g ^ (row&7)).
// ============================================================================
#define STAGE_BYTES 32768
#define SMEM_TOTAL  (2 * STAGE_BYTES)

__global__ __launch_bounds__(256, 1)
void gemm_tc(int mode, int kch, const float* __restrict__ u,
             const float* __restrict__ Dvec, float* __restrict__ out)
{
    extern __shared__ __align__(1024) char smem[];
    const int tid = threadIdx.x;
    const int lane = tid & 31, wid = tid >> 5;
    const int wm = wid >> 1, wn = wid & 1;      // 4 m-warps x 2 n-warps
    const int nBase = blockIdx.x * 128, mBase = blockIdx.y * 128;
    const uint32_t sb = smem_u32(smem);

    const __nv_bfloat16 *Ah, *Al, *Bh, *Bl;
    int lda, ldb;
    if (mode == 0) { Ah = g_uh; Al = g_ul; lda = 512;  Bh = g_B1hi; Bl = g_B1lo; ldb = 512; }
    else           { Ah = g_xh; Al = g_xl; lda = 1024; Bh = g_B2hi; Bl = g_B2lo; ldb = 1024; }

    // loader mapping: 2 threads per row; half 0 -> hi 64B, half 1 -> lo 64B
    const int r = tid >> 1, half = tid & 1;
    const int swz = r & 7;
    const __nv_bfloat16* aSrc = (half ? Al : Ah) + (size_t)(mBase + r) * lda;
    const __nv_bfloat16* bSrc = (half ? Bl : Bh) + (size_t)(nBase + r) * ldb;
    const uint32_t dstA = (uint32_t)r * 128;
    const uint32_t dstB = 16384u + (uint32_t)r * 128;

    // ldmatrix lane mapping
    const int g = lane >> 3, lr = lane & 7;
    int aRow[2], bRow[4];
#pragma unroll
    for (int mf = 0; mf < 2; mf++) aRow[mf] = wm * 32 + mf * 16 + (g & 1) * 8 + lr;
#pragma unroll
    for (int np = 0; np < 4; np++) bRow[np] = wn * 64 + np * 16 + (g >> 1) * 8 + lr;
    const int aCk = g >> 1;
    const int bCk = g & 1;

    float acc[2][8][4];
#pragma unroll
    for (int i = 0; i < 2; i++)
#pragma unroll
        for (int j = 0; j < 8; j++)
#pragma unroll
            for (int q = 0; q < 4; q++) acc[i][j][q] = 0.f;

    uint4 stgA[4], stgB[4];

    auto LDG = [&](int c) {
        const uint4* as = (const uint4*)(aSrc + c * 32);
        const uint4* bs = (const uint4*)(bSrc + c * 32);
#pragma unroll
        for (int j = 0; j < 4; j++) stgA[j] = as[j];
#pragma unroll
        for (int j = 0; j < 4; j++) stgB[j] = bs[j];
    };
    auto STS = [&](int s) {
        char* base = smem + s * STAGE_BYTES;
#pragma unroll
        for (int j = 0; j < 4; j++)
            *(uint4*)(base + dstA + (((half * 4 + j) ^ swz) << 4)) = stgA[j];
#pragma unroll
        for (int j = 0; j < 4; j++)
            *(uint4*)(base + dstB + (((half * 4 + j) ^ swz) << 4)) = stgB[j];
    };

    auto COMPUTE = [&](int s) {
        const uint32_t baseA = sb + s * STAGE_BYTES;
        const uint32_t baseB = baseA + 16384;
#pragma unroll
        for (int ks = 0; ks < 2; ks++) {
            uint32_t ah[2][4], al[2][4];
#pragma unroll
            for (int mf = 0; mf < 2; mf++) {
                const int rw = aRow[mf];
                ldsm4(ah[mf], baseA + rw * 128 + (((ks * 2 + aCk) ^ (rw & 7)) << 4));
                ldsm4(al[mf], baseA + rw * 128 + (((4 + ks * 2 + aCk) ^ (rw & 7)) << 4));
            }
            uint32_t bh[4][4], bl[4][4];
#pragma unroll
            for (int np = 0; np < 4; np++) {
                const int rw = bRow[np];
                ldsm4(bh[np], baseB + rw * 128 + (((ks * 2 + bCk) ^ (rw & 7)) << 4));
                ldsm4(bl[np], baseB + rw * 128 + (((4 + ks * 2 + bCk) ^ (rw & 7)) << 4));
            }
#pragma unroll
            for (int mf = 0; mf < 2; mf++)
#pragma unroll
                for (int np = 0; np < 4; np++) {
                    mma_bf16(acc[mf][2 * np],     ah[mf], &bh[np][0]);
                    mma_bf16(acc[mf][2 * np + 1], ah[mf], &bh[np][2]);
                    mma_bf16(acc[mf][2 * np],     ah[mf], &bl[np][0]);
                    mma_bf16(acc[mf][2 * np + 1], ah[mf], &bl[np][2]);
                    mma_bf16(acc[mf][2 * np],     al[mf], &bh[np][0]);
                    mma_bf16(acc[mf][2 * np + 1], al[mf], &bh[np][2]);
                }
        }
    };

    LDG(0);
    STS(0);
    __syncthreads();
    for (int c = 0; c < kch; c++) {
        if (c + 1 < kch) LDG(c + 1);
        COMPUTE(c & 1);
        if (c + 1 < kch) {
            __syncthreads();
            STS((c + 1) & 1);
            __syncthreads();
        }
    }

    // ---- epilogue ----
    const int em = lane >> 2, en = (lane & 3) * 2;
#pragma unroll
    for (int mf = 0; mf < 2; mf++)
#pragma unroll
        for (int nf = 0; nf < 8; nf++) {
            const int m = mBase + wm * 32 + mf * 16 + em;
            const int n = nBase + wn * 64 + nf * 8 + en;
            const float* a4 = acc[mf][nf];
            if (mode == 0) {
                float* dst = (n < 512) ? g_xre : g_xim;
                const int nc = n & 511;
                *(float2*)&dst[(size_t)m * 512 + nc]       = make_float2(a4[0], a4[1]);
                *(float2*)&dst[(size_t)(m + 8) * 512 + nc] = make_float2(a4[2], a4[3]);
            } else {
                float2 dd = *(const float2*)&Dvec[n];
                float2 u0 = *(const float2*)&u[(size_t)m * 512 + n];
                float2 u1 = *(const float2*)&u[(size_t)(m + 8) * 512 + n];
                *(float2*)&out[(size_t)m * 512 + n] =
                    make_float2(a4[0] + dd.x * u0.x, a4[1] + dd.y * u0.y);
                *(float2*)&out[(size_t)(m + 8) * 512 + n] =
                    make_float2(a4[2] + dd.x * u1.x, a4[3] + dd.y * u1.y);
            }
        }
}

// ============================================================================
// Scan phase 1: per-chunk local scan, in place; chunk 0 emits final bf16 split.
// ============================================================================
__global__ __launch_bounds__(512) void scan_local_kernel(
    const float* __restrict__ nu, const float* __restrict__ theta)
{
    const int n = threadIdx.x;
    const int c = blockIdx.x;
    const int b = blockIdx.y;
    const float r = expf(-expf(nu[n]));
    const float th = theta[n];
    const float lre = r * cosf(th), lim = r * sinf(th);
    float xr = 0.f, xi = 0.f;
    const size_t m0 = (size_t)b * TSEQ + (size_t)c * CHUNKT;
    const size_t base = m0 * NN + n;
    if (c == 0) {
#pragma unroll
        for (int t = 0; t < CHUNKT; t++) {
            size_t idx = base + (size_t)t * NN;
            float ur = g_xre[idx], ui = g_xim[idx];
            float nr = lre * xr - lim * xi + ur;
            float ni = lre * xi + lim * xr + ui;
            xr = nr; xi = ni;
            size_t mo = (m0 + t) * 1024 + n;
            __nv_bfloat16 h, l;
            splitbf(xr, h, l); g_xh[mo] = h;       g_xl[mo] = l;
            splitbf(xi, h, l); g_xh[mo + 512] = h; g_xl[mo + 512] = l;
        }
    } else {
#pragma unroll
        for (int t = 0; t < CHUNKT; t++) {
            size_t idx = base + (size_t)t * NN;
            float ur = g_xre[idx], ui = g_xim[idx];
            float nr = lre * xr - lim * xi + ur;
            float ni = lre * xi + lim * xr + ui;
            xr = nr; xi = ni;
            g_xre[idx] = xr; g_xim[idx] = xi;
        }
    }
    int coff = (b * NCHUNK + c) * NN + n;
    g_cre[coff] = xr; g_cim[coff] = xi;
}

// ============================================================================
// Scan phase 2: inclusive prefix over chunk carries (fully unrolled)
// ============================================================================
__global__ __launch_bounds__(512) void scan_chunk_kernel(
    const float* __restrict__ nu, const float* __restrict__ theta)
{
    const int n = threadIdx.x;
    const int b = blockIdx.x;
    const float e = expf(nu[n]);
    const float rP = expf(-(float)CHUNKT * e);
    const float ang = (float)CHUNKT * theta[n];
    const float Lre = rP * cosf(ang), Lim = rP * sinf(ang);
    float pr = 0.f, pi = 0.f;
#pragma unroll
    for (int c = 0; c < NCHUNK; c++) {
        int off = (b * NCHUNK + c) * NN + n;
        float cr = g_cre[off], ci = g_cim[off];
        float nr = Lre * pr - Lim * pi + cr;
        float ni = Lre * pi + Lim * pr + ci;
        pr = nr; pi = ni;
        g_pre[off] = pr; g_pim[off] = pi;
    }
}

// ============================================================================
// Scan phase 3: fixup chunks >=1 and emit final bf16 split for GEMM2.
// ============================================================================
__global__ __launch_bounds__(512) void scan_fix_kernel(
    const float* __restrict__ nu, const float* __restrict__ theta)
{
    const int n = threadIdx.x;
    const int c = blockIdx.x + 1;
    const int b = blockIdx.y;
    const float r = expf(-expf(nu[n]));
    const float th = theta[n];
    const float lre = r * cosf(th), lim = r * sinf(th);
    int poff = (b * NCHUNK + (c - 1)) * NN + n;
    float mr = g_pre[poff], mi = g_pim[poff];
    const size_t m0 = (size_t)b * TSEQ + (size_t)c * CHUNKT;
    const size_t base = m0 * NN + n;
#pragma unroll
    for (int t = 0; t < CHUNKT; t++) {
        float tr = lre * mr - lim * mi;
        float ti = lre * mi + lim * mr;
        mr = tr; mi = ti;
        size_t idx = base + (size_t)t * NN;
        float xr = g_xre[idx] + mr;
        float xi = g_xim[idx] + mi;
        size_t mo = (m0 + t) * 1024 + n;
        __nv_bfloat16 h, l;
        splitbf(xr, h, l); g_xh[mo] = h;       g_xl[mo] = l;
        splitbf(xi, h, l); g_xh[mo + 512] = h; g_xl[mo + 512] = l;
    }
}

// ============================================================================
extern "C" void kernel_launch(void* const* d_in, const int* in_sizes, int n_in,
                              void* d_out, int out_size)
{
    const float* u     = (const float*)d_in[0];
    const float* C_re  = (const float*)d_in[1];
    const float* C_im  = (const float*)d_in[2];
    const float* B_re  = (const float*)d_in[3];
    const float* B_im  = (const float*)d_in[4];
    const float* D     = (const float*)d_in[5];
    const float* nu    = (const float*)d_in[6];
    const float* theta = (const float*)d_in[7];
    const float* gamma = (const float*)d_in[8];
    float* out = (float*)d_out;

    cudaFuncSetAttribute(gemm_tc, cudaFuncAttributeMaxDynamicSharedMemorySize, SMEM_TOTAL);

    prep_kernel<<<dim3(16, 16, 4), dim3(32, 8)>>>(B_re, B_im, C_re, C_im, gamma);
    split_u_kernel<<<(MTOT * 512) / (256 * 8), 256>>>(u);
    gemm_tc<<<dim3(8, 128), 256, SMEM_TOTAL>>>(0, 16, u, D, out);
    scan_local_kernel<<<dim3(NCHUNK, NBATCH), NN>>>(nu, theta);
    scan_chunk_kernel<<<NBATCH, NN>>>(nu, theta);
    scan_fix_kernel<<<dim3(NCHUNK - 1, NBATCH), NN>>>(nu, theta);
    gemm_tc<<<dim3(4, 128), 256, SMEM_TOTAL>>>(1, 32, u, D, out);
}

// round 13
// speedup vs baseline: 3.0255x; 2.1890x over previous
#include <cuda_runtime.h>
#include <cuda_fp16.h>
#include <cstdint>

// Problem dims
#define MTOT   16384      // BATCH*T = 8*2048
#define NN     512
#define TSEQ   2048
#define NBATCH 8
#define NCHUNK 64
#define CHUNKT 32

// ---------------- scratch (__device__ globals; no allocs allowed) -----------
__device__ float g_xre[(size_t)MTOT * NN];      // GEMM1 out / scan intermediate
__device__ float g_xim[(size_t)MTOT * NN];
__device__ float g_cre[NBATCH * NCHUNK * NN];
__device__ float g_cim[NBATCH * NCHUNK * NN];
__device__ float g_pre[NBATCH * NCHUNK * NN];
__device__ float g_pim[NBATCH * NCHUNK * NN];

// fp16 operand panels
__device__ __align__(16) __half g_u16[(size_t)MTOT * 512];     // fp16(u)
__device__ __align__(16) __half g_x16[(size_t)MTOT * 1024];    // fp16([x_re | x_im])
// weights: g_B1 [1024 n'][512 k] = [(gamma B_re)^T ; (gamma B_im)^T]
//          g_B2 [512 n][1024 k]  = [C_re^T | (-C_im)^T]
__device__ __align__(16) __half g_B1[1024 * 512];
__device__ __align__(16) __half g_B2[512 * 1024];

// ---------------- helpers ---------------------------------------------------
__device__ __forceinline__ uint32_t smem_u32(const void* p) {
    uint32_t a;
    asm("{ .reg .u64 t; cvta.to.shared.u64 t, %1; cvt.u32.u64 %0, t; }"
        : "=r"(a) : "l"(p));
    return a;
}
__device__ __forceinline__ void ldsm4(uint32_t* r, uint32_t addr) {
    asm volatile("ldmatrix.sync.aligned.m8n8.x4.shared.b16 {%0,%1,%2,%3}, [%4];"
        : "=r"(r[0]), "=r"(r[1]), "=r"(r[2]), "=r"(r[3]) : "r"(addr));
}
__device__ __forceinline__ void mma_f16(float* c, const uint32_t* a, const uint32_t* b) {
    asm volatile("mma.sync.aligned.m16n8k16.row.col.f32.f16.f16.f32 "
        "{%0,%1,%2,%3}, {%4,%5,%6,%7}, {%8,%9}, {%0,%1,%2,%3};"
        : "+f"(c[0]), "+f"(c[1]), "+f"(c[2]), "+f"(c[3])
        : "r"(a[0]), "r"(a[1]), "r"(a[2]), "r"(a[3]), "r"(b[0]), "r"(b[1]));
}

// ============================================================================
// Prep: transpose + gamma-fold + fp16 convert of the 4 weight matrices
// ============================================================================
__global__ void prep_kernel(const float* __restrict__ Bre, const float* __restrict__ Bim,
                            const float* __restrict__ Cre, const float* __restrict__ Cim,
                            const float* __restrict__ gamma)
{
    __shared__ float tile[32][33];
    const int z = blockIdx.z;
    const float* S = (z == 0) ? Bre : (z == 1) ? Bim : (z == 2) ? Cre : Cim;
    const int k0 = blockIdx.x * 32, n0 = blockIdx.y * 32;
    const int tx = threadIdx.x, ty = threadIdx.y;  // 32 x 8
#pragma unroll
    for (int i = 0; i < 32; i += 8)
        tile[ty + i][tx] = S[(size_t)(k0 + ty + i) * 512 + n0 + tx];
    __syncthreads();
#pragma unroll
    for (int i = 0; i < 32; i += 8) {
        int n = n0 + ty + i, k = k0 + tx;
        float v = tile[tx][ty + i];
        if (z < 2)  v *= gamma[k];
        if (z == 3) v = -v;
        __half h = __float2half_rn(v);
        if (z == 0) g_B1[(size_t)n * 512 + k] = h;
        if (z == 1) g_B1[(size_t)(512 + n) * 512 + k] = h;
        if (z == 2) g_B2[(size_t)n * 1024 + k] = h;
        if (z == 3) g_B2[(size_t)n * 1024 + 512 + k] = h;
    }
}

// ============================================================================
// Convert u -> fp16 panel (one-time)
// ============================================================================
__global__ __launch_bounds__(256) void cvt_u_kernel(const float* __restrict__ u)
{
    size_t i = ((size_t)blockIdx.x * 256 + threadIdx.x) * 8;
    float4 v0 = *(const float4*)(u + i);
    float4 v1 = *(const float4*)(u + i + 4);
    uint32_t w[4];
    __half2* wp = (__half2*)w;
    wp[0] = __floats2half2_rn(v0.x, v0.y);
    wp[1] = __floats2half2_rn(v0.z, v0.w);
    wp[2] = __floats2half2_rn(v1.x, v1.y);
    wp[3] = __floats2half2_rn(v1.z, v1.w);
    *(uint4*)&g_u16[i] = make_uint4(w[0], w[1], w[2], w[3]);
}

// ============================================================================
// HMMA GEMM, fp16 operands (single product), fp32 accumulate.
// LDG->register->STS double buffer (R7-proven mainloop), BK=64.
// mode 0: D[16384,1024] = u @ B1^T           -> writes g_xre / g_xim (fp32)
// mode 1: D[16384, 512] = x @ B2^T           -> out = D + Dvec*u
// CTA tile M=128 N=128 K=64; 8 warps (warp tile 32x64); 2-stage smem.
// Stage: A 128 rows x 128B (64 fp16 of k), B same; 16B granule g of a row
// stored at (g ^ (row&7)).
// ============================================================================
#define STAGE_BYTES 32768
#define SMEM_TOTAL  (2 * STAGE_BYTES)

__global__ __launch_bounds__(256, 1)
void gemm_tc(int mode, int kch, const float* __restrict__ u,
             const float* __restrict__ Dvec, float* __restrict__ out)
{
    extern __shared__ __align__(1024) char smem[];
    const int tid = threadIdx.x;
    const int lane = tid & 31, wid = tid >> 5;
    const int wm = wid >> 1, wn = wid & 1;      // 4 m-warps x 2 n-warps
    const int nBase = blockIdx.x * 128, mBase = blockIdx.y * 128;
    const uint32_t sb = smem_u32(smem);

    const __half *Ap, *Bp;
    int lda, ldb;
    if (mode == 0) { Ap = g_u16; lda = 512;  Bp = g_B1; ldb = 512; }
    else           { Ap = g_x16; lda = 1024; Bp = g_B2; ldb = 1024; }

    // loader mapping: 2 threads per row; half h covers 64B (granules 4h..4h+3)
    const int r = tid >> 1, half = tid & 1;
    const int swz = r & 7;
    const __half* aSrc = Ap + (size_t)(mBase + r) * lda + half * 32;
    const __half* bSrc = Bp + (size_t)(nBase + r) * ldb + half * 32;
    const uint32_t dstA = (uint32_t)r * 128;
    const uint32_t dstB = 16384u + (uint32_t)r * 128;

    // ldmatrix lane mapping
    const int g = lane >> 3, lr = lane & 7;
    int aRow[2], bRow[4];
#pragma unroll
    for (int mf = 0; mf < 2; mf++) aRow[mf] = wm * 32 + mf * 16 + (g & 1) * 8 + lr;
#pragma unroll
    for (int np = 0; np < 4; np++) bRow[np] = wn * 64 + np * 16 + (g >> 1) * 8 + lr;
    const int aCk = g >> 1;
    const int bCk = g & 1;

    float acc[2][8][4];
#pragma unroll
    for (int i = 0; i < 2; i++)
#pragma unroll
        for (int j = 0; j < 8; j++)
#pragma unroll
            for (int q = 0; q < 4; q++) acc[i][j][q] = 0.f;

    uint4 stgA[4], stgB[4];

    auto LDG = [&](int c) {
        const uint4* as = (const uint4*)(aSrc + c * 64);
        const uint4* bs = (const uint4*)(bSrc + c * 64);
#pragma unroll
        for (int j = 0; j < 4; j++) stgA[j] = as[j];
#pragma unroll
        for (int j = 0; j < 4; j++) stgB[j] = bs[j];
    };
    auto STS = [&](int s) {
        char* base = smem + s * STAGE_BYTES;
#pragma unroll
        for (int j = 0; j < 4; j++)
            *(uint4*)(base + dstA + (((half * 4 + j) ^ swz) << 4)) = stgA[j];
#pragma unroll
        for (int j = 0; j < 4; j++)
            *(uint4*)(base + dstB + (((half * 4 + j) ^ swz) << 4)) = stgB[j];
    };

    auto COMPUTE = [&](int s) {
        const uint32_t baseA = sb + s * STAGE_BYTES;
        const uint32_t baseB = baseA + 16384;
#pragma unroll
        for (int ks = 0; ks < 4; ks++) {
            uint32_t af[2][4];
#pragma unroll
            for (int mf = 0; mf < 2; mf++) {
                const int rw = aRow[mf];
                ldsm4(af[mf], baseA + rw * 128 + (((ks * 2 + aCk) ^ (rw & 7)) << 4));
            }
            uint32_t bf[4][4];
#pragma unroll
            for (int np = 0; np < 4; np++) {
                const int rw = bRow[np];
                ldsm4(bf[np], baseB + rw * 128 + (((ks * 2 + bCk) ^ (rw & 7)) << 4));
            }
#pragma unroll
            for (int mf = 0; mf < 2; mf++)
#pragma unroll
                for (int np = 0; np < 4; np++) {
                    mma_f16(acc[mf][2 * np],     af[mf], &bf[np][0]);
                    mma_f16(acc[mf][2 * np + 1], af[mf], &bf[np][2]);
                }
        }
    };

    LDG(0);
    STS(0);
    __syncthreads();
    for (int c = 0; c < kch; c++) {
        if (c + 1 < kch) LDG(c + 1);
        COMPUTE(c & 1);
        if (c + 1 < kch) {
            __syncthreads();
            STS((c + 1) & 1);
            __syncthreads();
        }
    }

    // ---- epilogue ----
    const int em = lane >> 2, en = (lane & 3) * 2;
#pragma unroll
    for (int mf = 0; mf < 2; mf++)
#pragma unroll
        for (int nf = 0; nf < 8; nf++) {
            const int m = mBase + wm * 32 + mf * 16 + em;
            const int n = nBase + wn * 64 + nf * 8 + en;
            const float* a4 = acc[mf][nf];
            if (mode == 0) {
                float* dst = (n < 512) ? g_xre : g_xim;
                const int nc = n & 511;
                *(float2*)&dst[(size_t)m * 512 + nc]       = make_float2(a4[0], a4[1]);
                *(float2*)&dst[(size_t)(m + 8) * 512 + nc] = make_float2(a4[2], a4[3]);
            } else {
                float2 dd = *(const float2*)&Dvec[n];
                float2 u0 = *(const float2*)&u[(size_t)m * 512 + n];
                float2 u1 = *(const float2*)&u[(size_t)(m + 8) * 512 + n];
                *(float2*)&out[(size_t)m * 512 + n] =
                    make_float2(a4[0] + dd.x * u0.x, a4[1] + dd.y * u0.y);
                *(float2*)&out[(size_t)(m + 8) * 512 + n] =
                    make_float2(a4[2] + dd.x * u1.x, a4[3] + dd.y * u1.y);
            }
        }
}

// ============================================================================
// Scan phase 1: per-chunk local scan, in place; chunk 0 emits fp16 x directly.
// ============================================================================
__global__ __launch_bounds__(512) void scan_local_kernel(
    const float* __restrict__ nu, const float* __restrict__ theta)
{
    const int n = threadIdx.x;
    const int c = blockIdx.x;
    const int b = blockIdx.y;
    const float r = expf(-expf(nu[n]));
    const float th = theta[n];
    const float lre = r * cosf(th), lim = r * sinf(th);
    float xr = 0.f, xi = 0.f;
    const size_t m0 = (size_t)b * TSEQ + (size_t)c * CHUNKT;
    const size_t base = m0 * NN + n;
    if (c == 0) {
#pragma unroll
        for (int t = 0; t < CHUNKT; t++) {
            size_t idx = base + (size_t)t * NN;
            float ur = g_xre[idx], ui = g_xim[idx];
            float nr = lre * xr - lim * xi + ur;
            float ni = lre * xi + lim * xr + ui;
            xr = nr; xi = ni;
            size_t mo = (m0 + t) * 1024 + n;
            g_x16[mo]       = __float2half_rn(xr);
            g_x16[mo + 512] = __float2half_rn(xi);
        }
    } else {
#pragma unroll
        for (int t = 0; t < CHUNKT; t++) {
            size_t idx = base + (size_t)t * NN;
            float ur = g_xre[idx], ui = g_xim[idx];
            float nr = lre * xr - lim * xi + ur;
            float ni = lre * xi + lim * xr + ui;
            xr = nr; xi = ni;
            g_xre[idx] = xr; g_xim[idx] = xi;
        }
    }
    int coff = (b * NCHUNK + c) * NN + n;
    g_cre[coff] = xr; g_cim[coff] = xi;
}

// ============================================================================
// Scan phase 2: inclusive prefix over chunk carries (fully unrolled)
// ============================================================================
__global__ __launch_bounds__(512) void scan_chunk_kernel(
    const float* __restrict__ nu, const float* __restrict__ theta)
{
    const int n = threadIdx.x;
    const int b = blockIdx.x;
    const float e = expf(nu[n]);
    const float rP = expf(-(float)CHUNKT * e);
    const float ang = (float)CHUNKT * theta[n];
    const float Lre = rP * cosf(ang), Lim = rP * sinf(ang);
    float pr = 0.f, pi = 0.f;
#pragma unroll
    for (int c = 0; c < NCHUNK; c++) {
        int off = (b * NCHUNK + c) * NN + n;
        float cr = g_cre[off], ci = g_cim[off];
        float nr = Lre * pr - Lim * pi + cr;
        float ni = Lre * pi + Lim * pr + ci;
        pr = nr; pi = ni;
        g_pre[off] = pr; g_pim[off] = pi;
    }
}

// ============================================================================
// Scan phase 3: fixup chunks >=1 and emit fp16 x for GEMM2.
// ============================================================================
__global__ __launch_bounds__(512) void scan_fix_kernel(
    const float* __restrict__ nu, const float* __restrict__ theta)
{
    const int n = threadIdx.x;
    const int c = blockIdx.x + 1;
    const int b = blockIdx.y;
    const float r = expf(-expf(nu[n]));
    const float th = theta[n];
    const float lre = r * cosf(th), lim = r * sinf(th);
    int poff = (b * NCHUNK + (c - 1)) * NN + n;
    float mr = g_pre[poff], mi = g_pim[poff];
    const size_t m0 = (size_t)b * TSEQ + (size_t)c * CHUNKT;
    const size_t base = m0 * NN + n;
#pragma unroll
    for (int t = 0; t < CHUNKT; t++) {
        float tr = lre * mr - lim * mi;
        float ti = lre * mi + lim * mr;
        mr = tr; mi = ti;
        size_t idx = base + (size_t)t * NN;
        float xr = g_xre[idx] + mr;
        float xi = g_xim[idx] + mi;
        size_t mo = (m0 + t) * 1024 + n;
        g_x16[mo]       = __float2half_rn(xr);
        g_x16[mo + 512] = __float2half_rn(xi);
    }
}

// ============================================================================
extern "C" void kernel_launch(void* const* d_in, const int* in_sizes, int n_in,
                              void* d_out, int out_size)
{
    const float* u     = (const float*)d_in[0];
    const float* C_re  = (const float*)d_in[1];
    const float* C_im  = (const float*)d_in[2];
    const float* B_re  = (const float*)d_in[3];
    const float* B_im  = (const float*)d_in[4];
    const float* D     = (const float*)d_in[5];
    const float* nu    = (const float*)d_in[6];
    const float* theta = (const float*)d_in[7];
    const float* gamma = (const float*)d_in[8];
    float* out = (float*)d_out;

    cudaFuncSetAttribute(gemm_tc, cudaFuncAttributeMaxDynamicSharedMemorySize, SMEM_TOTAL);

    prep_kernel<<<dim3(16, 16, 4), dim3(32, 8)>>>(B_re, B_im, C_re, C_im, gamma);
    cvt_u_kernel<<<(MTOT * 512) / (256 * 8), 256>>>(u);
    gemm_tc<<<dim3(8, 128), 256, SMEM_TOTAL>>>(0, 8, u, D, out);
    scan_local_kernel<<<dim3(NCHUNK, NBATCH), NN>>>(nu, theta);
    scan_chunk_kernel<<<NBATCH, NN>>>(nu, theta);
    scan_fix_kernel<<<dim3(NCHUNK - 1, NBATCH), NN>>>(nu, theta);
    gemm_tc<<<dim3(4, 128), 256, SMEM_TOTAL>>>(1, 16, u, D, out);
}

// round 16
// speedup vs baseline: 3.3458x; 1.1059x over previous
#include <cuda_runtime.h>
#include <cuda_fp16.h>
#include <cstdint>

// Problem dims
#define MTOT   16384      // BATCH*T = 8*2048
#define NN     512
#define TSEQ   2048
#define NBATCH 8
#define NCHUNK 64
#define CHUNKT 32

// ---------------- scratch (__device__ globals; no allocs allowed) -----------
__device__ float g_cre[NBATCH * NCHUNK * NN];
__device__ float g_cim[NBATCH * NCHUNK * NN];
__device__ float g_pre[NBATCH * NCHUNK * NN];
__device__ float g_pim[NBATCH * NCHUNK * NN];

// fp16 operand panels
__device__ __align__(16) __half g_u16[(size_t)MTOT * 512];     // fp16(u)
// g_x16: [m][1024] = [re | im]; GEMM1 writes new_u here (fp16), scans update
// in place, GEMM2 reads the final x from it.
__device__ __align__(16) __half g_x16[(size_t)MTOT * 1024];
// weights: g_B1 [1024 n'][512 k] = [(gamma B_re)^T ; (gamma B_im)^T]
//          g_B2 [512 n][1024 k]  = [C_re^T | (-C_im)^T]
__device__ __align__(16) __half g_B1[1024 * 512];
__device__ __align__(16) __half g_B2[512 * 1024];

// ---------------- helpers ---------------------------------------------------
__device__ __forceinline__ uint32_t smem_u32(const void* p) {
    uint32_t a;
    asm("{ .reg .u64 t; cvta.to.shared.u64 t, %1; cvt.u32.u64 %0, t; }"
        : "=r"(a) : "l"(p));
    return a;
}
__device__ __forceinline__ void ldsm4(uint32_t* r, uint32_t addr) {
    asm volatile("ldmatrix.sync.aligned.m8n8.x4.shared.b16 {%0,%1,%2,%3}, [%4];"
        : "=r"(r[0]), "=r"(r[1]), "=r"(r[2]), "=r"(r[3]) : "r"(addr));
}
__device__ __forceinline__ void mma_f16(float* c, const uint32_t* a, const uint32_t* b) {
    asm volatile("mma.sync.aligned.m16n8k16.row.col.f32.f16.f16.f32 "
        "{%0,%1,%2,%3}, {%4,%5,%6,%7}, {%8,%9}, {%0,%1,%2,%3};"
        : "+f"(c[0]), "+f"(c[1]), "+f"(c[2]), "+f"(c[3])
        : "r"(a[0]), "r"(a[1]), "r"(a[2]), "r"(a[3]), "r"(b[0]), "r"(b[1]));
}

// ============================================================================
// Prep: transpose + gamma-fold + fp16 convert of the 4 weight matrices
// ============================================================================
__global__ void prep_kernel(const float* __restrict__ Bre, const float* __restrict__ Bim,
                            const float* __restrict__ Cre, const float* __restrict__ Cim,
                            const float* __restrict__ gamma)
{
    __shared__ float tile[32][33];
    const int z = blockIdx.z;
    const float* S = (z == 0) ? Bre : (z == 1) ? Bim : (z == 2) ? Cre : Cim;
    const int k0 = blockIdx.x * 32, n0 = blockIdx.y * 32;
    const int tx = threadIdx.x, ty = threadIdx.y;  // 32 x 8
#pragma unroll
    for (int i = 0; i < 32; i += 8)
        tile[ty + i][tx] = S[(size_t)(k0 + ty + i) * 512 + n0 + tx];
    __syncthreads();
#pragma unroll
    for (int i = 0; i < 32; i += 8) {
        int n = n0 + ty + i, k = k0 + tx;
        float v = tile[tx][ty + i];
        if (z < 2)  v *= gamma[k];
        if (z == 3) v = -v;
        __half h = __float2half_rn(v);
        if (z == 0) g_B1[(size_t)n * 512 + k] = h;
        if (z == 1) g_B1[(size_t)(512 + n) * 512 + k] = h;
        if (z == 2) g_B2[(size_t)n * 1024 + k] = h;
        if (z == 3) g_B2[(size_t)n * 1024 + 512 + k] = h;
    }
}

// ============================================================================
// Convert u -> fp16 panel (one-time)
// ============================================================================
__global__ __launch_bounds__(256) void cvt_u_kernel(const float* __restrict__ u)
{
    size_t i = ((size_t)blockIdx.x * 256 + threadIdx.x) * 8;
    float4 v0 = *(const float4*)(u + i);
    float4 v1 = *(const float4*)(u + i + 4);
    uint32_t w[4];
    __half2* wp = (__half2*)w;
    wp[0] = __floats2half2_rn(v0.x, v0.y);
    wp[1] = __floats2half2_rn(v0.z, v0.w);
    wp[2] = __floats2half2_rn(v1.x, v1.y);
    wp[3] = __floats2half2_rn(v1.z, v1.w);
    *(uint4*)&g_u16[i] = make_uint4(w[0], w[1], w[2], w[3]);
}

// ============================================================================
// HMMA GEMM, fp16 operands, fp32 accumulate. LDG->register->STS double buffer.
// mode 0: new_u[16384,1024] = u @ B1^T  -> writes g_x16 (fp16, [re|im] layout)
// mode 1: D[16384, 512] = x @ B2^T      -> out = D + Dvec*u
// CTA tile M=128 N=128 K=64; 8 warps (warp tile 32x64); 2-stage smem.
// ============================================================================
#define STAGE_BYTES 32768
#define SMEM_TOTAL  (2 * STAGE_BYTES)

__global__ __launch_bounds__(256, 1)
void gemm_tc(int mode, int kch, const float* __restrict__ u,
             const float* __restrict__ Dvec, float* __restrict__ out)
{
    extern __shared__ __align__(1024) char smem[];
    const int tid = threadIdx.x;
    const int lane = tid & 31, wid = tid >> 5;
    const int wm = wid >> 1, wn = wid & 1;      // 4 m-warps x 2 n-warps
    const int nBase = blockIdx.x * 128, mBase = blockIdx.y * 128;
    const uint32_t sb = smem_u32(smem);

    const __half *Ap, *Bp;
    int lda, ldb;
    if (mode == 0) { Ap = g_u16; lda = 512;  Bp = g_B1; ldb = 512; }
    else           { Ap = g_x16; lda = 1024; Bp = g_B2; ldb = 1024; }

    // loader mapping: 2 threads per row; half h covers 64B (granules 4h..4h+3)
    const int r = tid >> 1, half = tid & 1;
    const int swz = r & 7;
    const __half* aSrc = Ap + (size_t)(mBase + r) * lda + half * 32;
    const __half* bSrc = Bp + (size_t)(nBase + r) * ldb + half * 32;
    const uint32_t dstA = (uint32_t)r * 128;
    const uint32_t dstB = 16384u + (uint32_t)r * 128;

    // ldmatrix lane mapping
    const int g = lane >> 3, lr = lane & 7;
    int aRow[2], bRow[4];
#pragma unroll
    for (int mf = 0; mf < 2; mf++) aRow[mf] = wm * 32 + mf * 16 + (g & 1) * 8 + lr;
#pragma unroll
    for (int np = 0; np < 4; np++) bRow[np] = wn * 64 + np * 16 + (g >> 1) * 8 + lr;
    const int aCk = g >> 1;
    const int bCk = g & 1;

    float acc[2][8][4];
#pragma unroll
    for (int i = 0; i < 2; i++)
#pragma unroll
        for (int j = 0; j < 8; j++)
#pragma unroll
            for (int q = 0; q < 4; q++) acc[i][j][q] = 0.f;

    uint4 stgA[4], stgB[4];

    auto LDG = [&](int c) {
        const uint4* as = (const uint4*)(aSrc + c * 64);
        const uint4* bs = (const uint4*)(bSrc + c * 64);
#pragma unroll
        for (int j = 0; j < 4; j++) stgA[j] = as[j];
#pragma unroll
        for (int j = 0; j < 4; j++) stgB[j] = bs[j];
    };
    auto STS = [&](int s) {
        char* base = smem + s * STAGE_BYTES;
#pragma unroll
        for (int j = 0; j < 4; j++)
            *(uint4*)(base + dstA + (((half * 4 + j) ^ swz) << 4)) = stgA[j];
#pragma unroll
        for (int j = 0; j < 4; j++)
            *(uint4*)(base + dstB + (((half * 4 + j) ^ swz) << 4)) = stgB[j];
    };

    auto COMPUTE = [&](int s) {
        const uint32_t baseA = sb + s * STAGE_BYTES;
        const uint32_t baseB = baseA + 16384;
#pragma unroll
        for (int ks = 0; ks < 4; ks++) {
            uint32_t af[2][4];
#pragma unroll
            for (int mf = 0; mf < 2; mf++) {
                const int rw = aRow[mf];
                ldsm4(af[mf], baseA + rw * 128 + (((ks * 2 + aCk) ^ (rw & 7)) << 4));
            }
            uint32_t bf[4][4];
#pragma unroll
            for (int np = 0; np < 4; np++) {
                const int rw = bRow[np];
                ldsm4(bf[np], baseB + rw * 128 + (((ks * 2 + bCk) ^ (rw & 7)) << 4));
            }
#pragma unroll
            for (int mf = 0; mf < 2; mf++)
#pragma unroll
                for (int np = 0; np < 4; np++) {
                    mma_f16(acc[mf][2 * np],     af[mf], &bf[np][0]);
                    mma_f16(acc[mf][2 * np + 1], af[mf], &bf[np][2]);
                }
        }
    };

    LDG(0);
    STS(0);
    __syncthreads();
    for (int c = 0; c < kch; c++) {
        if (c + 1 < kch) LDG(c + 1);
        COMPUTE(c & 1);
        if (c + 1 < kch) {
            __syncthreads();
            STS((c + 1) & 1);
            __syncthreads();
        }
    }

    // ---- epilogue ----
    const int em = lane >> 2, en = (lane & 3) * 2;
#pragma unroll
    for (int mf = 0; mf < 2; mf++)
#pragma unroll
        for (int nf = 0; nf < 8; nf++) {
            const int m = mBase + wm * 32 + mf * 16 + em;
            const int n = nBase + wn * 64 + nf * 8 + en;
            const float* a4 = acc[mf][nf];
            if (mode == 0) {
                // new_u -> fp16, [re|im] layout is exactly m*1024 + n
                *(__half2*)&g_x16[(size_t)m * 1024 + n] =
                    __floats2half2_rn(a4[0], a4[1]);
                *(__half2*)&g_x16[(size_t)(m + 8) * 1024 + n] =
                    __floats2half2_rn(a4[2], a4[3]);
            } else {
                float2 dd = *(const float2*)&Dvec[n];
                float2 u0 = *(const float2*)&u[(size_t)m * 512 + n];
                float2 u1 = *(const float2*)&u[(size_t)(m + 8) * 512 + n];
                *(float2*)&out[(size_t)m * 512 + n] =
                    make_float2(a4[0] + dd.x * u0.x, a4[1] + dd.y * u0.y);
                *(float2*)&out[(size_t)(m + 8) * 512 + n] =
                    make_float2(a4[2] + dd.x * u1.x, a4[3] + dd.y * u1.y);
            }
        }
}

// ============================================================================
// Scan phase 1: per-chunk local scan over g_x16 in place (fp32 accumulators,
// fp16 storage); chunk-end carries stored fp32. 256 thr, 2 channels/thread.
// ============================================================================
__global__ __launch_bounds__(256) void scan_local_kernel(
    const float* __restrict__ nu, const float* __restrict__ theta)
{
    const int n2 = threadIdx.x;            // channel pair index
    const int n = n2 * 2;
    const int c = blockIdx.x;
    const int b = blockIdx.y;
    const float r0 = expf(-expf(nu[n])),     th0 = theta[n];
    const float r1 = expf(-expf(nu[n + 1])), th1 = theta[n + 1];
    const float lre0 = r0 * cosf(th0), lim0 = r0 * sinf(th0);
    const float lre1 = r1 * cosf(th1), lim1 = r1 * sinf(th1);
    float xr0 = 0.f, xi0 = 0.f, xr1 = 0.f, xi1 = 0.f;
    const size_t m0 = (size_t)b * TSEQ + (size_t)c * CHUNKT;
#pragma unroll
    for (int t = 0; t < CHUNKT; t++) {
        size_t row = (m0 + t) * 1024;
        float2 ur = __half22float2(*(__half2*)&g_x16[row + n]);
        float2 ui = __half22float2(*(__half2*)&g_x16[row + 512 + n]);
        float a0 = lre0 * xr0 - lim0 * xi0 + ur.x;
        float b0 = lre0 * xi0 + lim0 * xr0 + ui.x;
        float a1 = lre1 * xr1 - lim1 * xi1 + ur.y;
        float b1 = lre1 * xi1 + lim1 * xr1 + ui.y;
        xr0 = a0; xi0 = b0; xr1 = a1; xi1 = b1;
        *(__half2*)&g_x16[row + n]       = __floats2half2_rn(xr0, xr1);
        *(__half2*)&g_x16[row + 512 + n] = __floats2half2_rn(xi0, xi1);
    }
    int coff = (b * NCHUNK + c) * NN + n;
    g_cre[coff] = xr0; g_cre[coff + 1] = xr1;
    g_cim[coff] = xi0; g_cim[coff + 1] = xi1;
}

// ============================================================================
// Scan phase 2: inclusive prefix over chunk carries (fully unrolled)
// ============================================================================
__global__ __launch_bounds__(512) void scan_chunk_kernel(
    const float* __restrict__ nu, const float* __restrict__ theta)
{
    const int n = threadIdx.x;
    const int b = blockIdx.x;
    const float e = expf(nu[n]);
    const float rP = expf(-(float)CHUNKT * e);
    const float ang = (float)CHUNKT * theta[n];
    const float Lre = rP * cosf(ang), Lim = rP * sinf(ang);
    float pr = 0.f, pi = 0.f;
#pragma unroll
    for (int c = 0; c < NCHUNK; c++) {
        int off = (b * NCHUNK + c) * NN + n;
        float cr = g_cre[off], ci = g_cim[off];
        float nr = Lre * pr - Lim * pi + cr;
        float ni = Lre * pi + Lim * pr + ci;
        pr = nr; pi = ni;
        g_pre[off] = pr; g_pim[off] = pi;
    }
}

// ============================================================================
// Scan phase 3: fixup chunks >=1: x[t] += lam^{t+1} * P[c-1], fp16 in place.
// ============================================================================
__global__ __launch_bounds__(256) void scan_fix_kernel(
    const float* __restrict__ nu, const float* __restrict__ theta)
{
    const int n2 = threadIdx.x;
    const int n = n2 * 2;
    const int c = blockIdx.x + 1;
    const int b = blockIdx.y;
    const float r0 = expf(-expf(nu[n])),     th0 = theta[n];
    const float r1 = expf(-expf(nu[n + 1])), th1 = theta[n + 1];
    const float lre0 = r0 * cosf(th0), lim0 = r0 * sinf(th0);
    const float lre1 = r1 * cosf(th1), lim1 = r1 * sinf(th1);
    int poff = (b * NCHUNK + (c - 1)) * NN + n;
    float mr0 = g_pre[poff],     mi0 = g_pim[poff];
    float mr1 = g_pre[poff + 1], mi1 = g_pim[poff + 1];
    const size_t m0 = (size_t)b * TSEQ + (size_t)c * CHUNKT;
#pragma unroll
    for (int t = 0; t < CHUNKT; t++) {
        float a0 = lre0 * mr0 - lim0 * mi0;
        float b0 = lre0 * mi0 + lim0 * mr0;
        float a1 = lre1 * mr1 - lim1 * mi1;
        float b1 = lre1 * mi1 + lim1 * mr1;
        mr0 = a0; mi0 = b0; mr1 = a1; mi1 = b1;
        size_t row = (m0 + t) * 1024;
        float2 xr = __half22float2(*(__half2*)&g_x16[row + n]);
        float2 xi = __half22float2(*(__half2*)&g_x16[row + 512 + n]);
        *(__half2*)&g_x16[row + n]       = __floats2half2_rn(xr.x + mr0, xr.y + mr1);
        *(__half2*)&g_x16[row + 512 + n] = __floats2half2_rn(xi.x + mi0, xi.y + mi1);
    }
}

// ============================================================================
extern "C" void kernel_launch(void* const* d_in, const int* in_sizes, int n_in,
                              void* d_out, int out_size)
{
    const float* u     = (const float*)d_in[0];
    const float* C_re  = (const float*)d_in[1];
    const float* C_im  = (const float*)d_in[2];
    const float* B_re  = (const float*)d_in[3];
    const float* B_im  = (const float*)d_in[4];
    const float* D     = (const float*)d_in[5];
    const float* nu    = (const float*)d_in[6];
    const float* theta = (const float*)d_in[7];
    const float* gamma = (const float*)d_in[8];
    float* out = (float*)d_out;

    cudaFuncSetAttribute(gemm_tc, cudaFuncAttributeMaxDynamicSharedMemorySize, SMEM_TOTAL);

    prep_kernel<<<dim3(16, 16, 4), dim3(32, 8)>>>(B_re, B_im, C_re, C_im, gamma);
    cvt_u_kernel<<<(MTOT * 512) / (256 * 8), 256>>>(u);
    gemm_tc<<<dim3(8, 128), 256, SMEM_TOTAL>>>(0, 8, u, D, out);
    scan_local_kernel<<<dim3(NCHUNK, NBATCH), 256>>>(nu, theta);
    scan_chunk_kernel<<<NBATCH, NN>>>(nu, theta);
    scan_fix_kernel<<<dim3(NCHUNK - 1, NBATCH), 256>>>(nu, theta);
    gemm_tc<<<dim3(4, 128), 256, SMEM_TOTAL>>>(1, 16, u, D, out);
}